// round 12
// baseline (speedup 1.0000x reference)
#include <cuda_runtime.h>
#include <math.h>
#include <stdint.h>

// Problem constants
#define BB 2
#define TT 2048
#define CC 1024
#define HH 16
#define DD 64
#define CH 512
#define BT (BB*TT)          // 4096 rows

#define NEG_INF (__int_as_float(0xff800000))

// ---------------------------------------------------------------------------
// Scratch (device globals; reused across stages)
// ---------------------------------------------------------------------------
__device__ float g_bufA[BT*CH];    // h1
__device__ float g_bufB[BT*CC];    // xi -> v -> o
__device__ float g_bufC[BT*CC];    // rsnh -> q
__device__ float g_bufD[BT*CC];    // reasoned -> attnout
__device__ float g_bufE[BT*CC];    // k -> o (final proj)
__device__ float g_mean[BB*CC];
__device__ float g_temp[BB*HH];

// ---------------------------------------------------------------------------
// Helpers
// ---------------------------------------------------------------------------
__device__ __forceinline__ float gelu_exact(float x) {
    return 0.5f * x * (1.0f + erff(x * 0.7071067811865476f));
}

__device__ __forceinline__ float block_reduce_sum(float v, float* sbuf) {
    #pragma unroll
    for (int off = 16; off >= 1; off >>= 1)
        v += __shfl_xor_sync(0xffffffffu, v, off);
    int tid = threadIdx.x;
    int warp = tid >> 5, lane = tid & 31;
    int nw = blockDim.x >> 5;
    if (lane == 0) sbuf[warp] = v;
    __syncthreads();
    float s = (tid < nw) ? sbuf[tid] : 0.0f;
    if (warp == 0) {
        #pragma unroll
        for (int off = 16; off >= 1; off >>= 1)
            s += __shfl_xor_sync(0xffffffffu, s, off);
        if (lane == 0) sbuf[0] = s;
    }
    __syncthreads();
    float r = sbuf[0];
    __syncthreads();
    return r;
}

// ---------------------------------------------------------------------------
// SGEMM: Y[M,N] = A[M,K] @ W[K,N] + bias[N]
// 128x128x8 tile, 256 threads, 8x8 micro-tile (split 64-col groups).
// Requires M%128==0, N%128==0, K%8==0.
// ---------------------------------------------------------------------------
__global__ __launch_bounds__(256) void sgemm_bias(
    const float* __restrict__ A, const float* __restrict__ W,
    const float* __restrict__ bias, float* __restrict__ Y,
    int M, int N, int K)
{
    __shared__ float As[8][128];   // transposed A tile: As[k][m]
    __shared__ float Bs[8][128];   // Bs[k][n]

    int tid = threadIdx.x;
    int bx = blockIdx.x, by = blockIdx.y;
    int tx4 = (tid & 15) * 4;
    int ty4 = (tid >> 4) * 4;

    int a_row = tid >> 1;            // 0..127
    int a_col = (tid & 1) << 2;      // 0 or 4
    int b_row = tid >> 5;            // 0..7
    int b_col = (tid & 31) << 2;     // 0..124

    const float* Ab = A + (size_t)(by * 128) * K;
    const float* Wb = W + (size_t)(bx * 128);

    float acc[8][8];
    #pragma unroll
    for (int i = 0; i < 8; i++)
        #pragma unroll
        for (int j = 0; j < 8; j++) acc[i][j] = 0.0f;

    float4 a_next = *(const float4*)(Ab + (size_t)a_row * K + a_col);
    float4 b_next = *(const float4*)(Wb + (size_t)b_row * N + b_col);

    for (int k0 = 0; k0 < K; k0 += 8) {
        As[a_col + 0][a_row] = a_next.x;
        As[a_col + 1][a_row] = a_next.y;
        As[a_col + 2][a_row] = a_next.z;
        As[a_col + 3][a_row] = a_next.w;
        *(float4*)&Bs[b_row][b_col] = b_next;
        __syncthreads();

        if (k0 + 8 < K) {
            a_next = *(const float4*)(Ab + (size_t)a_row * K + (k0 + 8) + a_col);
            b_next = *(const float4*)(Wb + (size_t)(k0 + 8 + b_row) * N + b_col);
        }

        #pragma unroll
        for (int kk = 0; kk < 8; kk++) {
            float4 a0 = *(const float4*)&As[kk][ty4];
            float4 a1 = *(const float4*)&As[kk][64 + ty4];
            float4 b0 = *(const float4*)&Bs[kk][tx4];
            float4 b1 = *(const float4*)&Bs[kk][64 + tx4];
            float ra[8] = {a0.x, a0.y, a0.z, a0.w, a1.x, a1.y, a1.z, a1.w};
            float rb[8] = {b0.x, b0.y, b0.z, b0.w, b1.x, b1.y, b1.z, b1.w};
            #pragma unroll
            for (int i = 0; i < 8; i++)
                #pragma unroll
                for (int j = 0; j < 8; j++)
                    acc[i][j] += ra[i] * rb[j];
        }
        __syncthreads();
    }

    // Epilogue with bias
    #pragma unroll
    for (int i = 0; i < 8; i++) {
        int row = by * 128 + ((i < 4) ? (ty4 + i) : (64 + ty4 + i - 4));
        #pragma unroll
        for (int jg = 0; jg < 2; jg++) {
            int col = bx * 128 + jg * 64 + tx4;
            float4 o;
            o.x = acc[i][jg * 4 + 0] + bias[col + 0];
            o.y = acc[i][jg * 4 + 1] + bias[col + 1];
            o.z = acc[i][jg * 4 + 2] + bias[col + 2];
            o.w = acc[i][jg * 4 + 3] + bias[col + 3];
            *(float4*)(Y + (size_t)row * N + col) = o;
        }
    }
}

// ---------------------------------------------------------------------------
// Importance fuse: per row (BT rows):
//   y = GELU(LN(h1_row))   (len 512)
//   imp = max(sigmoid(dot(y, w2) + b2), 1e-6)
//   xi_row = x_row * imp   (len 1024)
// ---------------------------------------------------------------------------
__global__ __launch_bounds__(256) void imp_fuse(
    const float* __restrict__ h1, const float* __restrict__ g, const float* __restrict__ beta,
    const float* __restrict__ w2, const float* __restrict__ b2,
    const float* __restrict__ x, float* __restrict__ xi)
{
    __shared__ float sbuf[32];
    int row = blockIdx.x, tid = threadIdx.x;
    const float* hr = h1 + (size_t)row * CH;
    float v0 = hr[tid], v1 = hr[tid + 256];

    float s = block_reduce_sum(v0 + v1, sbuf);
    float mu = s * (1.0f / 512.0f);
    float d0 = v0 - mu, d1 = v1 - mu;
    float q = block_reduce_sum(d0 * d0 + d1 * d1, sbuf);
    float rstd = rsqrtf(q * (1.0f / 512.0f) + 1e-5f);

    float y0 = gelu_exact(d0 * rstd * g[tid] + beta[tid]);
    float y1 = gelu_exact(d1 * rstd * g[tid + 256] + beta[tid + 256]);

    float part = y0 * w2[tid] + y1 * w2[tid + 256];
    float dot = block_reduce_sum(part, sbuf);
    float z = dot + b2[0];
    float imp = 1.0f / (1.0f + __expf(-z));
    imp = fmaxf(imp, 1e-6f);

    const float* xr = x + (size_t)row * CC;
    float* xir = xi + (size_t)row * CC;
    #pragma unroll
    for (int i = 0; i < 4; i++)
        xir[tid + i * 256] = xr[tid + i * 256] * imp;
}

// ---------------------------------------------------------------------------
// In-place LN + GELU over rows of length 1024
// ---------------------------------------------------------------------------
__global__ __launch_bounds__(256) void ln_gelu_1024(
    float* __restrict__ h, const float* __restrict__ g, const float* __restrict__ beta)
{
    __shared__ float sbuf[32];
    int row = blockIdx.x, tid = threadIdx.x;
    float* hr = h + (size_t)row * CC;
    float v[4];
    #pragma unroll
    for (int i = 0; i < 4; i++) v[i] = hr[tid + i * 256];

    float s = block_reduce_sum(v[0] + v[1] + v[2] + v[3], sbuf);
    float mu = s * (1.0f / 1024.0f);
    float q = 0.0f;
    #pragma unroll
    for (int i = 0; i < 4; i++) { float d = v[i] - mu; q += d * d; }
    q = block_reduce_sum(q, sbuf);
    float rstd = rsqrtf(q * (1.0f / 1024.0f) + 1e-5f);

    #pragma unroll
    for (int i = 0; i < 4; i++) {
        int c = tid + i * 256;
        float y = (v[i] - mu) * rstd * g[c] + beta[c];
        hr[c] = gelu_exact(y);
    }
}

// ---------------------------------------------------------------------------
// Mean over T: reasoned[B,T,C] -> mean[B,C]
// ---------------------------------------------------------------------------
__global__ __launch_bounds__(256) void mean_kernel(
    const float* __restrict__ r, float* __restrict__ out)
{
    int idx = blockIdx.x * 256 + threadIdx.x;   // 0..2047
    int b = idx >> 10, c = idx & 1023;
    const float* p = r + (size_t)b * TT * CC + c;
    float s = 0.0f;
    #pragma unroll 8
    for (int t = 0; t < TT; t++) s += p[(size_t)t * CC];
    out[idx] = s * (1.0f / (float)TT);
}

// ---------------------------------------------------------------------------
// Temperature net: mean[B,C] -> temp[B,H]. One block per batch, 512 threads.
// ---------------------------------------------------------------------------
__global__ __launch_bounds__(512) void temp_kernel(
    const float* __restrict__ mean, const float* __restrict__ w1, const float* __restrict__ b1,
    const float* __restrict__ g, const float* __restrict__ beta,
    const float* __restrict__ w2, const float* __restrict__ b2,
    float* __restrict__ temp)
{
    __shared__ float xm[CC];
    __shared__ float hb[CH];
    __shared__ float sbuf[32];
    int b = blockIdx.x, tid = threadIdx.x;
    for (int i = tid; i < CC; i += 512) xm[i] = mean[b * CC + i];
    __syncthreads();

    float acc = b1[tid];
    #pragma unroll 8
    for (int i = 0; i < CC; i++) acc += xm[i] * w1[(size_t)i * CH + tid];

    float s = block_reduce_sum(acc, sbuf);
    float mu = s * (1.0f / 512.0f);
    float d = acc - mu;
    float q = block_reduce_sum(d * d, sbuf);
    float rstd = rsqrtf(q * (1.0f / 512.0f) + 1e-5f);
    float y = gelu_exact(d * rstd * g[tid] + beta[tid]);
    hb[tid] = y;
    __syncthreads();

    if (tid < HH) {
        float a = b2[tid];
        for (int i = 0; i < CH; i++) a += hb[i] * w2[i * HH + tid];
        float sp = (a > 20.0f) ? a : log1pf(__expf(a));
        temp[b * HH + tid] = sp + 0.5f;
    }
}

// ---------------------------------------------------------------------------
// Flash attention (fp32). Grid: (T/128, B*H). 256 threads.
// q,k,v laid out [B,T,C] with head slice h*64..h*64+63.
// ---------------------------------------------------------------------------
#define FBM 128
#define FBN 64
#define QS 132
#define KSS 68
#define PSr 68

__global__ __launch_bounds__(256) void flash_attn(
    const float* __restrict__ q, const float* __restrict__ k, const float* __restrict__ v,
    const int* __restrict__ mask, const float* __restrict__ temp,
    float* __restrict__ out)
{
    extern __shared__ float sm[];
    float* Qt = sm;                 // [64][QS]   (d-major, 128 rows)
    float* Kt = Qt + 64 * QS;       // [64][KSS]  (d-major, 64 cols)
    float* Vs = Kt + 64 * KSS;      // [64][64]   (c-major)
    float* Ps = Vs + 64 * 64;       // [128][PSr] (r-major)

    int tid = threadIdx.x;
    int tx4 = (tid & 15) * 4;
    int ty4 = (tid >> 4) * 4;
    int bh = blockIdx.y;
    int b = bh >> 4, h = bh & 15;
    int q0 = blockIdx.x * FBM;

    const float* qbase = q + (size_t)b * TT * CC + h * DD;
    const float* kbase = k + (size_t)b * TT * CC + h * DD;
    const float* vbase = v + (size_t)b * TT * CC + h * DD;
    const int*   mbase = mask + (size_t)b * TT * TT;

    float tfac = temp[bh] * 0.125f;   // 1/sqrt(64) * temp

    // Load Q tile transposed: Qt[d][r]
    for (int idx = tid; idx < FBM * DD; idx += 256) {
        int r = idx >> 6, d = idx & 63;
        Qt[d * QS + r] = qbase[(size_t)(q0 + r) * CC + d];
    }

    float m_i[8], l_i[8], Oacc[8][4];
    #pragma unroll
    for (int i = 0; i < 8; i++) {
        m_i[i] = NEG_INF; l_i[i] = 0.0f;
        #pragma unroll
        for (int j = 0; j < 4; j++) Oacc[i][j] = 0.0f;
    }

    for (int kt = 0; kt < TT; kt += FBN) {
        __syncthreads();   // prev O-gemm done with Vs/Ps; (first iter: Qt visible)
        for (int idx = tid; idx < FBN * DD; idx += 256) {
            int c = idx >> 6, d = idx & 63;
            float kv = kbase[(size_t)(kt + c) * CC + d];
            float vv = vbase[(size_t)(kt + c) * CC + d];
            Kt[d * KSS + c] = kv;
            Vs[c * 64 + d]  = vv;
        }
        __syncthreads();

        // S[8][4] = Q tile rows x K tile cols
        float S[8][4];
        #pragma unroll
        for (int i = 0; i < 8; i++)
            #pragma unroll
            for (int j = 0; j < 4; j++) S[i][j] = 0.0f;

        #pragma unroll 8
        for (int d = 0; d < 64; d++) {
            float4 a0 = *(const float4*)&Qt[d * QS + ty4];
            float4 a1 = *(const float4*)&Qt[d * QS + 64 + ty4];
            float4 bb = *(const float4*)&Kt[d * KSS + tx4];
            float ra[8] = {a0.x, a0.y, a0.z, a0.w, a1.x, a1.y, a1.z, a1.w};
            float rb[4] = {bb.x, bb.y, bb.z, bb.w};
            #pragma unroll
            for (int i = 0; i < 8; i++)
                #pragma unroll
                for (int j = 0; j < 4; j++)
                    S[i][j] += ra[i] * rb[j];
        }

        // mask + scale*temp
        #pragma unroll
        for (int i = 0; i < 8; i++) {
            int rg = q0 + ((i < 4) ? (ty4 + i) : (64 + ty4 + i - 4));
            const int* mr = mbase + (size_t)rg * TT + kt + tx4;
            #pragma unroll
            for (int j = 0; j < 4; j++)
                S[i][j] = (mr[j] != 0) ? S[i][j] * tfac : NEG_INF;
        }

        // online softmax per row (row owned by 16 consecutive lanes)
        #pragma unroll
        for (int i = 0; i < 8; i++) {
            float mx = fmaxf(fmaxf(S[i][0], S[i][1]), fmaxf(S[i][2], S[i][3]));
            #pragma unroll
            for (int off = 8; off >= 1; off >>= 1)
                mx = fmaxf(mx, __shfl_xor_sync(0xffffffffu, mx, off, 16));
            float mnew = fmaxf(m_i[i], mx);
            float corr = __expf(m_i[i] - mnew);
            float ps = 0.0f;
            #pragma unroll
            for (int j = 0; j < 4; j++) {
                float e = __expf(S[i][j] - mnew);
                S[i][j] = e;
                ps += e;
            }
            #pragma unroll
            for (int off = 8; off >= 1; off >>= 1)
                ps += __shfl_xor_sync(0xffffffffu, ps, off, 16);
            l_i[i] = l_i[i] * corr + ps;
            m_i[i] = mnew;
            #pragma unroll
            for (int j = 0; j < 4; j++) Oacc[i][j] *= corr;
        }

        // write P to smem (row-major, conflict-free float4)
        #pragma unroll
        for (int i = 0; i < 8; i++) {
            int rl = (i < 4) ? (ty4 + i) : (64 + ty4 + i - 4);
            *(float4*)&Ps[rl * PSr + tx4] = make_float4(S[i][0], S[i][1], S[i][2], S[i][3]);
        }
        __syncthreads();

        // O += P @ V   (thread: 8 rows x 4 d-cols)
        for (int c = 0; c < 64; c += 4) {
            float4 pv[8];
            #pragma unroll
            for (int i = 0; i < 8; i++) {
                int rl = (i < 4) ? (ty4 + i) : (64 + ty4 + i - 4);
                pv[i] = *(const float4*)&Ps[rl * PSr + c];
            }
            float4 vv[4];
            #pragma unroll
            for (int cc = 0; cc < 4; cc++)
                vv[cc] = *(const float4*)&Vs[(c + cc) * 64 + tx4];
            #pragma unroll
            for (int i = 0; i < 8; i++) {
                float pr[4] = {pv[i].x, pv[i].y, pv[i].z, pv[i].w};
                #pragma unroll
                for (int cc = 0; cc < 4; cc++) {
                    Oacc[i][0] += pr[cc] * vv[cc].x;
                    Oacc[i][1] += pr[cc] * vv[cc].y;
                    Oacc[i][2] += pr[cc] * vv[cc].z;
                    Oacc[i][3] += pr[cc] * vv[cc].w;
                }
            }
        }
    }

    // normalize and write out: [B,T,C] layout
    #pragma unroll
    for (int i = 0; i < 8; i++) {
        float inv = 1.0f / l_i[i];
        int rg = q0 + ((i < 4) ? (ty4 + i) : (64 + ty4 + i - 4));
        float4 o = make_float4(Oacc[i][0] * inv, Oacc[i][1] * inv,
                               Oacc[i][2] * inv, Oacc[i][3] * inv);
        *(float4*)(out + (size_t)(b * TT + rg) * CC + h * DD + tx4) = o;
    }
}

// ---------------------------------------------------------------------------
// Final residual LN: y = LN(x + o) * g + b
// ---------------------------------------------------------------------------
__global__ __launch_bounds__(256) void final_ln(
    const float* __restrict__ x, const float* __restrict__ o,
    const float* __restrict__ g, const float* __restrict__ beta,
    float* __restrict__ out)
{
    __shared__ float sbuf[32];
    int row = blockIdx.x, tid = threadIdx.x;
    const float* xr = x + (size_t)row * CC;
    const float* orr = o + (size_t)row * CC;
    float v[4];
    #pragma unroll
    for (int i = 0; i < 4; i++) v[i] = xr[tid + i * 256] + orr[tid + i * 256];

    float s = block_reduce_sum(v[0] + v[1] + v[2] + v[3], sbuf);
    float mu = s * (1.0f / 1024.0f);
    float q = 0.0f;
    #pragma unroll
    for (int i = 0; i < 4; i++) { float d = v[i] - mu; q += d * d; }
    q = block_reduce_sum(q, sbuf);
    float rstd = rsqrtf(q * (1.0f / 1024.0f) + 1e-5f);

    float* yr = out + (size_t)row * CC;
    #pragma unroll
    for (int i = 0; i < 4; i++) {
        int c = tid + i * 256;
        yr[c] = (v[i] - mu) * rstd * g[c] + beta[c];
    }
}

// ---------------------------------------------------------------------------
// Launch
// ---------------------------------------------------------------------------
extern "C" void kernel_launch(void* const* d_in, const int* in_sizes, int n_in,
                              void* d_out, int out_size)
{
    const float* x        = (const float*)d_in[0];
    const int*   mask     = (const int*)  d_in[1];
    const float* imp_w1   = (const float*)d_in[2];
    const float* imp_b1   = (const float*)d_in[3];
    const float* imp_g    = (const float*)d_in[4];
    const float* imp_beta = (const float*)d_in[5];
    const float* imp_w2   = (const float*)d_in[6];
    const float* imp_b2   = (const float*)d_in[7];
    const float* rsn_w1   = (const float*)d_in[8];
    const float* rsn_b1   = (const float*)d_in[9];
    const float* rsn_g    = (const float*)d_in[10];
    const float* rsn_beta = (const float*)d_in[11];
    const float* rsn_w2   = (const float*)d_in[12];
    const float* rsn_b2   = (const float*)d_in[13];
    const float* q_w      = (const float*)d_in[14];
    const float* q_b      = (const float*)d_in[15];
    const float* k_w      = (const float*)d_in[16];
    const float* k_b      = (const float*)d_in[17];
    const float* v_w      = (const float*)d_in[18];
    const float* v_b      = (const float*)d_in[19];
    const float* o_w      = (const float*)d_in[20];
    const float* o_b      = (const float*)d_in[21];
    const float* tmp_w1   = (const float*)d_in[22];
    const float* tmp_b1   = (const float*)d_in[23];
    const float* tmp_g    = (const float*)d_in[24];
    const float* tmp_beta = (const float*)d_in[25];
    const float* tmp_w2   = (const float*)d_in[26];
    const float* tmp_b2   = (const float*)d_in[27];
    const float* norm_g   = (const float*)d_in[28];
    const float* norm_b   = (const float*)d_in[29];

    float *bufA, *bufB, *bufC, *bufD, *bufE, *meanb, *tempb;
    cudaGetSymbolAddress((void**)&bufA, g_bufA);
    cudaGetSymbolAddress((void**)&bufB, g_bufB);
    cudaGetSymbolAddress((void**)&bufC, g_bufC);
    cudaGetSymbolAddress((void**)&bufD, g_bufD);
    cudaGetSymbolAddress((void**)&bufE, g_bufE);
    cudaGetSymbolAddress((void**)&meanb, g_mean);
    cudaGetSymbolAddress((void**)&tempb, g_temp);

    // 1. h1 = x @ imp_w1 + b1                       [4096,512]
    sgemm_bias<<<dim3(CH/128, BT/128), 256>>>(x, imp_w1, imp_b1, bufA, BT, CH, CC);
    // 2. importance gate -> xi                       [4096,1024]
    imp_fuse<<<BT, 256>>>(bufA, imp_g, imp_beta, imp_w2, imp_b2, x, bufB);
    // 3. rsnh = xi @ rsn_w1 + b
    sgemm_bias<<<dim3(CC/128, BT/128), 256>>>(bufB, rsn_w1, rsn_b1, bufC, BT, CC, CC);
    // 4. rsnh = GELU(LN(rsnh))
    ln_gelu_1024<<<BT, 256>>>(bufC, rsn_g, rsn_beta);
    // 5. reasoned = rsnh @ rsn_w2 + b
    sgemm_bias<<<dim3(CC/128, BT/128), 256>>>(bufC, rsn_w2, rsn_b2, bufD, BT, CC, CC);
    // 6. q = reasoned @ q_w + b   (overwrites rsnh)
    sgemm_bias<<<dim3(CC/128, BT/128), 256>>>(bufD, q_w, q_b, bufC, BT, CC, CC);
    // 7. k = xi @ k_w + b
    sgemm_bias<<<dim3(CC/128, BT/128), 256>>>(bufB, k_w, k_b, bufE, BT, CC, CC);
    // 8. v = x @ v_w + b          (overwrites xi)
    sgemm_bias<<<dim3(CC/128, BT/128), 256>>>(x, v_w, v_b, bufB, BT, CC, CC);
    // 9. mean over T of reasoned
    mean_kernel<<<(BB*CC)/256, 256>>>(bufD, meanb);
    // 10. temperature
    temp_kernel<<<BB, 512>>>(meanb, tmp_w1, tmp_b1, tmp_g, tmp_beta, tmp_w2, tmp_b2, tempb);
    // 11. flash attention -> attnout (overwrites reasoned)
    {
        int smemBytes = (64*QS + 64*KSS + 64*64 + 128*PSr) * (int)sizeof(float);
        cudaFuncSetAttribute(flash_attn, cudaFuncAttributeMaxDynamicSharedMemorySize, smemBytes);
        flash_attn<<<dim3(TT/FBM, BB*HH), 256, smemBytes>>>(bufC, bufE, bufB, mask, tempb, bufD);
    }
    // 12. o = attnout @ o_w + b   (overwrites k)
    sgemm_bias<<<dim3(CC/128, BT/128), 256>>>(bufD, o_w, o_b, bufE, BT, CC, CC);
    // 13. out = LN(x + o)
    final_ln<<<BT, 256>>>(x, bufE, norm_g, norm_b, (float*)d_out);
}

// round 13
// speedup vs baseline: 1.0070x; 1.0070x over previous
#include <cuda_runtime.h>
#include <math.h>
#include <stdint.h>

// Problem constants
#define BB 2
#define TT 2048
#define CC 1024
#define HH 16
#define DD 64
#define CH 512
#define BT (BB*TT)          // 4096 rows

#define NEG_INF (__int_as_float(0xff800000))

// ---------------------------------------------------------------------------
// Scratch (device globals; reused across stages)
// ---------------------------------------------------------------------------
__device__ float g_bufA[BT*CH];    // h1
__device__ float g_bufB[BT*CC];    // xi -> v -> o
__device__ float g_bufC[BT*CC];    // rsnh -> q
__device__ float g_bufD[BT*CC];    // reasoned -> attnout
__device__ float g_bufE[BT*CC];    // k -> o (final proj)
__device__ float g_mean[BB*CC];
__device__ float g_temp[BB*HH];

// ---------------------------------------------------------------------------
// Helpers
// ---------------------------------------------------------------------------
__device__ __forceinline__ float gelu_exact(float x) {
    return 0.5f * x * (1.0f + erff(x * 0.7071067811865476f));
}

__device__ __forceinline__ float block_reduce_sum(float v, float* sbuf) {
    #pragma unroll
    for (int off = 16; off >= 1; off >>= 1)
        v += __shfl_xor_sync(0xffffffffu, v, off);
    int tid = threadIdx.x;
    int warp = tid >> 5, lane = tid & 31;
    int nw = blockDim.x >> 5;
    if (lane == 0) sbuf[warp] = v;
    __syncthreads();
    float s = (tid < nw) ? sbuf[tid] : 0.0f;
    if (warp == 0) {
        #pragma unroll
        for (int off = 16; off >= 1; off >>= 1)
            s += __shfl_xor_sync(0xffffffffu, s, off);
        if (lane == 0) sbuf[0] = s;
    }
    __syncthreads();
    float r = sbuf[0];
    __syncthreads();
    return r;
}

// ---------------------------------------------------------------------------
// SGEMM: Y[M,N] = A[M,K] @ W[K,N] + bias[N]
// 128x128x8 tile, 256 threads, 8x8 micro-tile (split 64-col groups).
// Requires M%128==0, N%128==0, K%8==0.
// ---------------------------------------------------------------------------
__global__ __launch_bounds__(256) void sgemm_bias(
    const float* __restrict__ A, const float* __restrict__ W,
    const float* __restrict__ bias, float* __restrict__ Y,
    int M, int N, int K)
{
    __shared__ float As[8][128];   // transposed A tile: As[k][m]
    __shared__ float Bs[8][128];   // Bs[k][n]

    int tid = threadIdx.x;
    int bx = blockIdx.x, by = blockIdx.y;
    int tx4 = (tid & 15) * 4;
    int ty4 = (tid >> 4) * 4;

    int a_row = tid >> 1;            // 0..127
    int a_col = (tid & 1) << 2;      // 0 or 4
    int b_row = tid >> 5;            // 0..7
    int b_col = (tid & 31) << 2;     // 0..124

    const float* Ab = A + (size_t)(by * 128) * K;
    const float* Wb = W + (size_t)(bx * 128);

    float acc[8][8];
    #pragma unroll
    for (int i = 0; i < 8; i++)
        #pragma unroll
        for (int j = 0; j < 8; j++) acc[i][j] = 0.0f;

    float4 a_next = *(const float4*)(Ab + (size_t)a_row * K + a_col);
    float4 b_next = *(const float4*)(Wb + (size_t)b_row * N + b_col);

    for (int k0 = 0; k0 < K; k0 += 8) {
        As[a_col + 0][a_row] = a_next.x;
        As[a_col + 1][a_row] = a_next.y;
        As[a_col + 2][a_row] = a_next.z;
        As[a_col + 3][a_row] = a_next.w;
        *(float4*)&Bs[b_row][b_col] = b_next;
        __syncthreads();

        if (k0 + 8 < K) {
            a_next = *(const float4*)(Ab + (size_t)a_row * K + (k0 + 8) + a_col);
            b_next = *(const float4*)(Wb + (size_t)(k0 + 8 + b_row) * N + b_col);
        }

        #pragma unroll
        for (int kk = 0; kk < 8; kk++) {
            float4 a0 = *(const float4*)&As[kk][ty4];
            float4 a1 = *(const float4*)&As[kk][64 + ty4];
            float4 b0 = *(const float4*)&Bs[kk][tx4];
            float4 b1 = *(const float4*)&Bs[kk][64 + tx4];
            float ra[8] = {a0.x, a0.y, a0.z, a0.w, a1.x, a1.y, a1.z, a1.w};
            float rb[8] = {b0.x, b0.y, b0.z, b0.w, b1.x, b1.y, b1.z, b1.w};
            #pragma unroll
            for (int i = 0; i < 8; i++)
                #pragma unroll
                for (int j = 0; j < 8; j++)
                    acc[i][j] += ra[i] * rb[j];
        }
        __syncthreads();
    }

    // Epilogue with bias
    #pragma unroll
    for (int i = 0; i < 8; i++) {
        int row = by * 128 + ((i < 4) ? (ty4 + i) : (64 + ty4 + i - 4));
        #pragma unroll
        for (int jg = 0; jg < 2; jg++) {
            int col = bx * 128 + jg * 64 + tx4;
            float4 o;
            o.x = acc[i][jg * 4 + 0] + bias[col + 0];
            o.y = acc[i][jg * 4 + 1] + bias[col + 1];
            o.z = acc[i][jg * 4 + 2] + bias[col + 2];
            o.w = acc[i][jg * 4 + 3] + bias[col + 3];
            *(float4*)(Y + (size_t)row * N + col) = o;
        }
    }
}

// ---------------------------------------------------------------------------
// Importance fuse: per row (BT rows):
//   y = GELU(LN(h1_row))   (len 512)
//   imp = max(sigmoid(dot(y, w2) + b2), 1e-6)
//   xi_row = x_row * imp   (len 1024)
// ---------------------------------------------------------------------------
__global__ __launch_bounds__(256) void imp_fuse(
    const float* __restrict__ h1, const float* __restrict__ g, const float* __restrict__ beta,
    const float* __restrict__ w2, const float* __restrict__ b2,
    const float* __restrict__ x, float* __restrict__ xi)
{
    __shared__ float sbuf[32];
    int row = blockIdx.x, tid = threadIdx.x;
    const float* hr = h1 + (size_t)row * CH;
    float v0 = hr[tid], v1 = hr[tid + 256];

    float s = block_reduce_sum(v0 + v1, sbuf);
    float mu = s * (1.0f / 512.0f);
    float d0 = v0 - mu, d1 = v1 - mu;
    float q = block_reduce_sum(d0 * d0 + d1 * d1, sbuf);
    float rstd = rsqrtf(q * (1.0f / 512.0f) + 1e-5f);

    float y0 = gelu_exact(d0 * rstd * g[tid] + beta[tid]);
    float y1 = gelu_exact(d1 * rstd * g[tid + 256] + beta[tid + 256]);

    float part = y0 * w2[tid] + y1 * w2[tid + 256];
    float dot = block_reduce_sum(part, sbuf);
    float z = dot + b2[0];
    float imp = 1.0f / (1.0f + __expf(-z));
    imp = fmaxf(imp, 1e-6f);

    const float* xr = x + (size_t)row * CC;
    float* xir = xi + (size_t)row * CC;
    #pragma unroll
    for (int i = 0; i < 4; i++)
        xir[tid + i * 256] = xr[tid + i * 256] * imp;
}

// ---------------------------------------------------------------------------
// In-place LN + GELU over rows of length 1024
// ---------------------------------------------------------------------------
__global__ __launch_bounds__(256) void ln_gelu_1024(
    float* __restrict__ h, const float* __restrict__ g, const float* __restrict__ beta)
{
    __shared__ float sbuf[32];
    int row = blockIdx.x, tid = threadIdx.x;
    float* hr = h + (size_t)row * CC;
    float v[4];
    #pragma unroll
    for (int i = 0; i < 4; i++) v[i] = hr[tid + i * 256];

    float s = block_reduce_sum(v[0] + v[1] + v[2] + v[3], sbuf);
    float mu = s * (1.0f / 1024.0f);
    float q = 0.0f;
    #pragma unroll
    for (int i = 0; i < 4; i++) { float d = v[i] - mu; q += d * d; }
    q = block_reduce_sum(q, sbuf);
    float rstd = rsqrtf(q * (1.0f / 1024.0f) + 1e-5f);

    #pragma unroll
    for (int i = 0; i < 4; i++) {
        int c = tid + i * 256;
        float y = (v[i] - mu) * rstd * g[c] + beta[c];
        hr[c] = gelu_exact(y);
    }
}

// ---------------------------------------------------------------------------
// Mean over T: reasoned[B,T,C] -> mean[B,C]
// ---------------------------------------------------------------------------
__global__ __launch_bounds__(256) void mean_kernel(
    const float* __restrict__ r, float* __restrict__ out)
{
    int idx = blockIdx.x * 256 + threadIdx.x;   // 0..2047
    int b = idx >> 10, c = idx & 1023;
    const float* p = r + (size_t)b * TT * CC + c;
    float s = 0.0f;
    #pragma unroll 8
    for (int t = 0; t < TT; t++) s += p[(size_t)t * CC];
    out[idx] = s * (1.0f / (float)TT);
}

// ---------------------------------------------------------------------------
// Temperature net: mean[B,C] -> temp[B,H]. One block per batch, 512 threads.
// ---------------------------------------------------------------------------
__global__ __launch_bounds__(512) void temp_kernel(
    const float* __restrict__ mean, const float* __restrict__ w1, const float* __restrict__ b1,
    const float* __restrict__ g, const float* __restrict__ beta,
    const float* __restrict__ w2, const float* __restrict__ b2,
    float* __restrict__ temp)
{
    __shared__ float xm[CC];
    __shared__ float hb[CH];
    __shared__ float sbuf[32];
    int b = blockIdx.x, tid = threadIdx.x;
    for (int i = tid; i < CC; i += 512) xm[i] = mean[b * CC + i];
    __syncthreads();

    float acc = b1[tid];
    #pragma unroll 8
    for (int i = 0; i < CC; i++) acc += xm[i] * w1[(size_t)i * CH + tid];

    float s = block_reduce_sum(acc, sbuf);
    float mu = s * (1.0f / 512.0f);
    float d = acc - mu;
    float q = block_reduce_sum(d * d, sbuf);
    float rstd = rsqrtf(q * (1.0f / 512.0f) + 1e-5f);
    float y = gelu_exact(d * rstd * g[tid] + beta[tid]);
    hb[tid] = y;
    __syncthreads();

    if (tid < HH) {
        float a = b2[tid];
        for (int i = 0; i < CH; i++) a += hb[i] * w2[i * HH + tid];
        float sp = (a > 20.0f) ? a : log1pf(__expf(a));
        temp[b * HH + tid] = sp + 0.5f;
    }
}

// ---------------------------------------------------------------------------
// Flash attention (fp32). Grid: (T/128, B*H). 256 threads.
// q,k,v laid out [B,T,C] with head slice h*64..h*64+63.
// ---------------------------------------------------------------------------
#define FBM 128
#define FBN 64
#define QS 132
#define KSS 68
#define PSr 68

__global__ __launch_bounds__(256) void flash_attn(
    const float* __restrict__ q, const float* __restrict__ k, const float* __restrict__ v,
    const int* __restrict__ mask, const float* __restrict__ temp,
    float* __restrict__ out)
{
    extern __shared__ float sm[];
    float* Qt = sm;                 // [64][QS]   (d-major, 128 rows)
    float* Kt = Qt + 64 * QS;       // [64][KSS]  (d-major, 64 cols)
    float* Vs = Kt + 64 * KSS;      // [64][64]   (c-major)
    float* Ps = Vs + 64 * 64;       // [128][PSr] (r-major)

    int tid = threadIdx.x;
    int tx4 = (tid & 15) * 4;
    int ty4 = (tid >> 4) * 4;
    int bh = blockIdx.y;
    int b = bh >> 4, h = bh & 15;
    int q0 = blockIdx.x * FBM;

    const float* qbase = q + (size_t)b * TT * CC + h * DD;
    const float* kbase = k + (size_t)b * TT * CC + h * DD;
    const float* vbase = v + (size_t)b * TT * CC + h * DD;
    const int*   mbase = mask + (size_t)b * TT * TT;

    float tfac = temp[bh] * 0.125f;   // 1/sqrt(64) * temp

    // Load Q tile transposed: Qt[d][r]
    for (int idx = tid; idx < FBM * DD; idx += 256) {
        int r = idx >> 6, d = idx & 63;
        Qt[d * QS + r] = qbase[(size_t)(q0 + r) * CC + d];
    }

    float m_i[8], l_i[8], Oacc[8][4];
    #pragma unroll
    for (int i = 0; i < 8; i++) {
        m_i[i] = NEG_INF; l_i[i] = 0.0f;
        #pragma unroll
        for (int j = 0; j < 4; j++) Oacc[i][j] = 0.0f;
    }

    for (int kt = 0; kt < TT; kt += FBN) {
        __syncthreads();   // prev O-gemm done with Vs/Ps; (first iter: Qt visible)
        for (int idx = tid; idx < FBN * DD; idx += 256) {
            int c = idx >> 6, d = idx & 63;
            float kv = kbase[(size_t)(kt + c) * CC + d];
            float vv = vbase[(size_t)(kt + c) * CC + d];
            Kt[d * KSS + c] = kv;
            Vs[c * 64 + d]  = vv;
        }
        __syncthreads();

        // S[8][4] = Q tile rows x K tile cols
        float S[8][4];
        #pragma unroll
        for (int i = 0; i < 8; i++)
            #pragma unroll
            for (int j = 0; j < 4; j++) S[i][j] = 0.0f;

        #pragma unroll 8
        for (int d = 0; d < 64; d++) {
            float4 a0 = *(const float4*)&Qt[d * QS + ty4];
            float4 a1 = *(const float4*)&Qt[d * QS + 64 + ty4];
            float4 bb = *(const float4*)&Kt[d * KSS + tx4];
            float ra[8] = {a0.x, a0.y, a0.z, a0.w, a1.x, a1.y, a1.z, a1.w};
            float rb[4] = {bb.x, bb.y, bb.z, bb.w};
            #pragma unroll
            for (int i = 0; i < 8; i++)
                #pragma unroll
                for (int j = 0; j < 4; j++)
                    S[i][j] += ra[i] * rb[j];
        }

        // mask + scale*temp
        #pragma unroll
        for (int i = 0; i < 8; i++) {
            int rg = q0 + ((i < 4) ? (ty4 + i) : (64 + ty4 + i - 4));
            const int* mr = mbase + (size_t)rg * TT + kt + tx4;
            #pragma unroll
            for (int j = 0; j < 4; j++)
                S[i][j] = (mr[j] != 0) ? S[i][j] * tfac : NEG_INF;
        }

        // online softmax per row (row owned by 16 consecutive lanes)
        #pragma unroll
        for (int i = 0; i < 8; i++) {
            float mx = fmaxf(fmaxf(S[i][0], S[i][1]), fmaxf(S[i][2], S[i][3]));
            #pragma unroll
            for (int off = 8; off >= 1; off >>= 1)
                mx = fmaxf(mx, __shfl_xor_sync(0xffffffffu, mx, off, 16));
            float mnew = fmaxf(m_i[i], mx);
            float corr = __expf(m_i[i] - mnew);
            float ps = 0.0f;
            #pragma unroll
            for (int j = 0; j < 4; j++) {
                float e = __expf(S[i][j] - mnew);
                S[i][j] = e;
                ps += e;
            }
            #pragma unroll
            for (int off = 8; off >= 1; off >>= 1)
                ps += __shfl_xor_sync(0xffffffffu, ps, off, 16);
            l_i[i] = l_i[i] * corr + ps;
            m_i[i] = mnew;
            #pragma unroll
            for (int j = 0; j < 4; j++) Oacc[i][j] *= corr;
        }

        // write P to smem (row-major, conflict-free float4)
        #pragma unroll
        for (int i = 0; i < 8; i++) {
            int rl = (i < 4) ? (ty4 + i) : (64 + ty4 + i - 4);
            *(float4*)&Ps[rl * PSr + tx4] = make_float4(S[i][0], S[i][1], S[i][2], S[i][3]);
        }
        __syncthreads();

        // O += P @ V   (thread: 8 rows x 4 d-cols)
        for (int c = 0; c < 64; c += 4) {
            float4 pv[8];
            #pragma unroll
            for (int i = 0; i < 8; i++) {
                int rl = (i < 4) ? (ty4 + i) : (64 + ty4 + i - 4);
                pv[i] = *(const float4*)&Ps[rl * PSr + c];
            }
            float4 vv[4];
            #pragma unroll
            for (int cc = 0; cc < 4; cc++)
                vv[cc] = *(const float4*)&Vs[(c + cc) * 64 + tx4];
            #pragma unroll
            for (int i = 0; i < 8; i++) {
                float pr[4] = {pv[i].x, pv[i].y, pv[i].z, pv[i].w};
                #pragma unroll
                for (int cc = 0; cc < 4; cc++) {
                    Oacc[i][0] += pr[cc] * vv[cc].x;
                    Oacc[i][1] += pr[cc] * vv[cc].y;
                    Oacc[i][2] += pr[cc] * vv[cc].z;
                    Oacc[i][3] += pr[cc] * vv[cc].w;
                }
            }
        }
    }

    // normalize and write out: [B,T,C] layout
    #pragma unroll
    for (int i = 0; i < 8; i++) {
        float inv = 1.0f / l_i[i];
        int rg = q0 + ((i < 4) ? (ty4 + i) : (64 + ty4 + i - 4));
        float4 o = make_float4(Oacc[i][0] * inv, Oacc[i][1] * inv,
                               Oacc[i][2] * inv, Oacc[i][3] * inv);
        *(float4*)(out + (size_t)(b * TT + rg) * CC + h * DD + tx4) = o;
    }
}

// ---------------------------------------------------------------------------
// Final residual LN: y = LN(x + o) * g + b
// ---------------------------------------------------------------------------
__global__ __launch_bounds__(256) void final_ln(
    const float* __restrict__ x, const float* __restrict__ o,
    const float* __restrict__ g, const float* __restrict__ beta,
    float* __restrict__ out)
{
    __shared__ float sbuf[32];
    int row = blockIdx.x, tid = threadIdx.x;
    const float* xr = x + (size_t)row * CC;
    const float* orr = o + (size_t)row * CC;
    float v[4];
    #pragma unroll
    for (int i = 0; i < 4; i++) v[i] = xr[tid + i * 256] + orr[tid + i * 256];

    float s = block_reduce_sum(v[0] + v[1] + v[2] + v[3], sbuf);
    float mu = s * (1.0f / 1024.0f);
    float q = 0.0f;
    #pragma unroll
    for (int i = 0; i < 4; i++) { float d = v[i] - mu; q += d * d; }
    q = block_reduce_sum(q, sbuf);
    float rstd = rsqrtf(q * (1.0f / 1024.0f) + 1e-5f);

    float* yr = out + (size_t)row * CC;
    #pragma unroll
    for (int i = 0; i < 4; i++) {
        int c = tid + i * 256;
        yr[c] = (v[i] - mu) * rstd * g[c] + beta[c];
    }
}

// ---------------------------------------------------------------------------
// Launch
// ---------------------------------------------------------------------------
extern "C" void kernel_launch(void* const* d_in, const int* in_sizes, int n_in,
                              void* d_out, int out_size)
{
    const float* x        = (const float*)d_in[0];
    const int*   mask     = (const int*)  d_in[1];
    const float* imp_w1   = (const float*)d_in[2];
    const float* imp_b1   = (const float*)d_in[3];
    const float* imp_g    = (const float*)d_in[4];
    const float* imp_beta = (const float*)d_in[5];
    const float* imp_w2   = (const float*)d_in[6];
    const float* imp_b2   = (const float*)d_in[7];
    const float* rsn_w1   = (const float*)d_in[8];
    const float* rsn_b1   = (const float*)d_in[9];
    const float* rsn_g    = (const float*)d_in[10];
    const float* rsn_beta = (const float*)d_in[11];
    const float* rsn_w2   = (const float*)d_in[12];
    const float* rsn_b2   = (const float*)d_in[13];
    const float* q_w      = (const float*)d_in[14];
    const float* q_b      = (const float*)d_in[15];
    const float* k_w      = (const float*)d_in[16];
    const float* k_b      = (const float*)d_in[17];
    const float* v_w      = (const float*)d_in[18];
    const float* v_b      = (const float*)d_in[19];
    const float* o_w      = (const float*)d_in[20];
    const float* o_b      = (const float*)d_in[21];
    const float* tmp_w1   = (const float*)d_in[22];
    const float* tmp_b1   = (const float*)d_in[23];
    const float* tmp_g    = (const float*)d_in[24];
    const float* tmp_beta = (const float*)d_in[25];
    const float* tmp_w2   = (const float*)d_in[26];
    const float* tmp_b2   = (const float*)d_in[27];
    const float* norm_g   = (const float*)d_in[28];
    const float* norm_b   = (const float*)d_in[29];

    float *bufA, *bufB, *bufC, *bufD, *bufE, *meanb, *tempb;
    cudaGetSymbolAddress((void**)&bufA, g_bufA);
    cudaGetSymbolAddress((void**)&bufB, g_bufB);
    cudaGetSymbolAddress((void**)&bufC, g_bufC);
    cudaGetSymbolAddress((void**)&bufD, g_bufD);
    cudaGetSymbolAddress((void**)&bufE, g_bufE);
    cudaGetSymbolAddress((void**)&meanb, g_mean);
    cudaGetSymbolAddress((void**)&tempb, g_temp);

    // 1. h1 = x @ imp_w1 + b1                       [4096,512]
    sgemm_bias<<<dim3(CH/128, BT/128), 256>>>(x, imp_w1, imp_b1, bufA, BT, CH, CC);
    // 2. importance gate -> xi                       [4096,1024]
    imp_fuse<<<BT, 256>>>(bufA, imp_g, imp_beta, imp_w2, imp_b2, x, bufB);
    // 3. rsnh = xi @ rsn_w1 + b
    sgemm_bias<<<dim3(CC/128, BT/128), 256>>>(bufB, rsn_w1, rsn_b1, bufC, BT, CC, CC);
    // 4. rsnh = GELU(LN(rsnh))
    ln_gelu_1024<<<BT, 256>>>(bufC, rsn_g, rsn_beta);
    // 5. reasoned = rsnh @ rsn_w2 + b
    sgemm_bias<<<dim3(CC/128, BT/128), 256>>>(bufC, rsn_w2, rsn_b2, bufD, BT, CC, CC);
    // 6. q = reasoned @ q_w + b   (overwrites rsnh)
    sgemm_bias<<<dim3(CC/128, BT/128), 256>>>(bufD, q_w, q_b, bufC, BT, CC, CC);
    // 7. k = xi @ k_w + b
    sgemm_bias<<<dim3(CC/128, BT/128), 256>>>(bufB, k_w, k_b, bufE, BT, CC, CC);
    // 8. v = x @ v_w + b          (overwrites xi)
    sgemm_bias<<<dim3(CC/128, BT/128), 256>>>(x, v_w, v_b, bufB, BT, CC, CC);
    // 9. mean over T of reasoned
    mean_kernel<<<(BB*CC)/256, 256>>>(bufD, meanb);
    // 10. temperature
    temp_kernel<<<BB, 512>>>(meanb, tmp_w1, tmp_b1, tmp_g, tmp_beta, tmp_w2, tmp_b2, tempb);
    // 11. flash attention -> attnout (overwrites reasoned)
    {
        int smemBytes = (64*QS + 64*KSS + 64*64 + 128*PSr) * (int)sizeof(float);
        cudaFuncSetAttribute(flash_attn, cudaFuncAttributeMaxDynamicSharedMemorySize, smemBytes);
        flash_attn<<<dim3(TT/FBM, BB*HH), 256, smemBytes>>>(bufC, bufE, bufB, mask, tempb, bufD);
    }
    // 12. o = attnout @ o_w + b   (overwrites k)
    sgemm_bias<<<dim3(CC/128, BT/128), 256>>>(bufD, o_w, o_b, bufE, BT, CC, CC);
    // 13. out = LN(x + o)
    final_ln<<<BT, 256>>>(x, bufE, norm_g, norm_b, (float*)d_out);
}

// round 14
// speedup vs baseline: 1.0077x; 1.0007x over previous
#include <cuda_runtime.h>
#include <math.h>
#include <stdint.h>

// Problem constants
#define BB 2
#define TT 2048
#define CC 1024
#define HH 16
#define DD 64
#define CH 512
#define BT (BB*TT)          // 4096 rows

#define NEG_INF (__int_as_float(0xff800000))

// ---------------------------------------------------------------------------
// Scratch (device globals; reused across stages)
// ---------------------------------------------------------------------------
__device__ float g_bufA[BT*CH];    // h1
__device__ float g_bufB[BT*CC];    // xi -> v -> o
__device__ float g_bufC[BT*CC];    // rsnh -> q
__device__ float g_bufD[BT*CC];    // reasoned -> attnout
__device__ float g_bufE[BT*CC];    // k -> o (final proj)
__device__ float g_mean[BB*CC];
__device__ float g_temp[BB*HH];

// ---------------------------------------------------------------------------
// Helpers
// ---------------------------------------------------------------------------
__device__ __forceinline__ float gelu_exact(float x) {
    return 0.5f * x * (1.0f + erff(x * 0.7071067811865476f));
}

__device__ __forceinline__ float block_reduce_sum(float v, float* sbuf) {
    #pragma unroll
    for (int off = 16; off >= 1; off >>= 1)
        v += __shfl_xor_sync(0xffffffffu, v, off);
    int tid = threadIdx.x;
    int warp = tid >> 5, lane = tid & 31;
    int nw = blockDim.x >> 5;
    if (lane == 0) sbuf[warp] = v;
    __syncthreads();
    float s = (tid < nw) ? sbuf[tid] : 0.0f;
    if (warp == 0) {
        #pragma unroll
        for (int off = 16; off >= 1; off >>= 1)
            s += __shfl_xor_sync(0xffffffffu, s, off);
        if (lane == 0) sbuf[0] = s;
    }
    __syncthreads();
    float r = sbuf[0];
    __syncthreads();
    return r;
}

// ---------------------------------------------------------------------------
// SGEMM: Y[M,N] = A[M,K] @ W[K,N] + bias[N]
// 128x128x8 tile, 256 threads, 8x8 micro-tile (split 64-col groups).
// Requires M%128==0, N%128==0, K%8==0.
// ---------------------------------------------------------------------------
__global__ __launch_bounds__(256) void sgemm_bias(
    const float* __restrict__ A, const float* __restrict__ W,
    const float* __restrict__ bias, float* __restrict__ Y,
    int M, int N, int K)
{
    __shared__ float As[8][128];   // transposed A tile: As[k][m]
    __shared__ float Bs[8][128];   // Bs[k][n]

    int tid = threadIdx.x;
    int bx = blockIdx.x, by = blockIdx.y;
    int tx4 = (tid & 15) * 4;
    int ty4 = (tid >> 4) * 4;

    int a_row = tid >> 1;            // 0..127
    int a_col = (tid & 1) << 2;      // 0 or 4
    int b_row = tid >> 5;            // 0..7
    int b_col = (tid & 31) << 2;     // 0..124

    const float* Ab = A + (size_t)(by * 128) * K;
    const float* Wb = W + (size_t)(bx * 128);

    float acc[8][8];
    #pragma unroll
    for (int i = 0; i < 8; i++)
        #pragma unroll
        for (int j = 0; j < 8; j++) acc[i][j] = 0.0f;

    float4 a_next = *(const float4*)(Ab + (size_t)a_row * K + a_col);
    float4 b_next = *(const float4*)(Wb + (size_t)b_row * N + b_col);

    for (int k0 = 0; k0 < K; k0 += 8) {
        As[a_col + 0][a_row] = a_next.x;
        As[a_col + 1][a_row] = a_next.y;
        As[a_col + 2][a_row] = a_next.z;
        As[a_col + 3][a_row] = a_next.w;
        *(float4*)&Bs[b_row][b_col] = b_next;
        __syncthreads();

        if (k0 + 8 < K) {
            a_next = *(const float4*)(Ab + (size_t)a_row * K + (k0 + 8) + a_col);
            b_next = *(const float4*)(Wb + (size_t)(k0 + 8 + b_row) * N + b_col);
        }

        #pragma unroll
        for (int kk = 0; kk < 8; kk++) {
            float4 a0 = *(const float4*)&As[kk][ty4];
            float4 a1 = *(const float4*)&As[kk][64 + ty4];
            float4 b0 = *(const float4*)&Bs[kk][tx4];
            float4 b1 = *(const float4*)&Bs[kk][64 + tx4];
            float ra[8] = {a0.x, a0.y, a0.z, a0.w, a1.x, a1.y, a1.z, a1.w};
            float rb[8] = {b0.x, b0.y, b0.z, b0.w, b1.x, b1.y, b1.z, b1.w};
            #pragma unroll
            for (int i = 0; i < 8; i++)
                #pragma unroll
                for (int j = 0; j < 8; j++)
                    acc[i][j] += ra[i] * rb[j];
        }
        __syncthreads();
    }

    // Epilogue with bias
    #pragma unroll
    for (int i = 0; i < 8; i++) {
        int row = by * 128 + ((i < 4) ? (ty4 + i) : (64 + ty4 + i - 4));
        #pragma unroll
        for (int jg = 0; jg < 2; jg++) {
            int col = bx * 128 + jg * 64 + tx4;
            float4 o;
            o.x = acc[i][jg * 4 + 0] + bias[col + 0];
            o.y = acc[i][jg * 4 + 1] + bias[col + 1];
            o.z = acc[i][jg * 4 + 2] + bias[col + 2];
            o.w = acc[i][jg * 4 + 3] + bias[col + 3];
            *(float4*)(Y + (size_t)row * N + col) = o;
        }
    }
}

// ---------------------------------------------------------------------------
// Importance fuse: per row (BT rows):
//   y = GELU(LN(h1_row))   (len 512)
//   imp = max(sigmoid(dot(y, w2) + b2), 1e-6)
//   xi_row = x_row * imp   (len 1024)
// ---------------------------------------------------------------------------
__global__ __launch_bounds__(256) void imp_fuse(
    const float* __restrict__ h1, const float* __restrict__ g, const float* __restrict__ beta,
    const float* __restrict__ w2, const float* __restrict__ b2,
    const float* __restrict__ x, float* __restrict__ xi)
{
    __shared__ float sbuf[32];
    int row = blockIdx.x, tid = threadIdx.x;
    const float* hr = h1 + (size_t)row * CH;
    float v0 = hr[tid], v1 = hr[tid + 256];

    float s = block_reduce_sum(v0 + v1, sbuf);
    float mu = s * (1.0f / 512.0f);
    float d0 = v0 - mu, d1 = v1 - mu;
    float q = block_reduce_sum(d0 * d0 + d1 * d1, sbuf);
    float rstd = rsqrtf(q * (1.0f / 512.0f) + 1e-5f);

    float y0 = gelu_exact(d0 * rstd * g[tid] + beta[tid]);
    float y1 = gelu_exact(d1 * rstd * g[tid + 256] + beta[tid + 256]);

    float part = y0 * w2[tid] + y1 * w2[tid + 256];
    float dot = block_reduce_sum(part, sbuf);
    float z = dot + b2[0];
    float imp = 1.0f / (1.0f + __expf(-z));
    imp = fmaxf(imp, 1e-6f);

    const float* xr = x + (size_t)row * CC;
    float* xir = xi + (size_t)row * CC;
    #pragma unroll
    for (int i = 0; i < 4; i++)
        xir[tid + i * 256] = xr[tid + i * 256] * imp;
}

// ---------------------------------------------------------------------------
// In-place LN + GELU over rows of length 1024
// ---------------------------------------------------------------------------
__global__ __launch_bounds__(256) void ln_gelu_1024(
    float* __restrict__ h, const float* __restrict__ g, const float* __restrict__ beta)
{
    __shared__ float sbuf[32];
    int row = blockIdx.x, tid = threadIdx.x;
    float* hr = h + (size_t)row * CC;
    float v[4];
    #pragma unroll
    for (int i = 0; i < 4; i++) v[i] = hr[tid + i * 256];

    float s = block_reduce_sum(v[0] + v[1] + v[2] + v[3], sbuf);
    float mu = s * (1.0f / 1024.0f);
    float q = 0.0f;
    #pragma unroll
    for (int i = 0; i < 4; i++) { float d = v[i] - mu; q += d * d; }
    q = block_reduce_sum(q, sbuf);
    float rstd = rsqrtf(q * (1.0f / 1024.0f) + 1e-5f);

    #pragma unroll
    for (int i = 0; i < 4; i++) {
        int c = tid + i * 256;
        float y = (v[i] - mu) * rstd * g[c] + beta[c];
        hr[c] = gelu_exact(y);
    }
}

// ---------------------------------------------------------------------------
// Mean over T: reasoned[B,T,C] -> mean[B,C]
// ---------------------------------------------------------------------------
__global__ __launch_bounds__(256) void mean_kernel(
    const float* __restrict__ r, float* __restrict__ out)
{
    int idx = blockIdx.x * 256 + threadIdx.x;   // 0..2047
    int b = idx >> 10, c = idx & 1023;
    const float* p = r + (size_t)b * TT * CC + c;
    float s = 0.0f;
    #pragma unroll 8
    for (int t = 0; t < TT; t++) s += p[(size_t)t * CC];
    out[idx] = s * (1.0f / (float)TT);
}

// ---------------------------------------------------------------------------
// Temperature net: mean[B,C] -> temp[B,H]. One block per batch, 512 threads.
// ---------------------------------------------------------------------------
__global__ __launch_bounds__(512) void temp_kernel(
    const float* __restrict__ mean, const float* __restrict__ w1, const float* __restrict__ b1,
    const float* __restrict__ g, const float* __restrict__ beta,
    const float* __restrict__ w2, const float* __restrict__ b2,
    float* __restrict__ temp)
{
    __shared__ float xm[CC];
    __shared__ float hb[CH];
    __shared__ float sbuf[32];
    int b = blockIdx.x, tid = threadIdx.x;
    for (int i = tid; i < CC; i += 512) xm[i] = mean[b * CC + i];
    __syncthreads();

    float acc = b1[tid];
    #pragma unroll 8
    for (int i = 0; i < CC; i++) acc += xm[i] * w1[(size_t)i * CH + tid];

    float s = block_reduce_sum(acc, sbuf);
    float mu = s * (1.0f / 512.0f);
    float d = acc - mu;
    float q = block_reduce_sum(d * d, sbuf);
    float rstd = rsqrtf(q * (1.0f / 512.0f) + 1e-5f);
    float y = gelu_exact(d * rstd * g[tid] + beta[tid]);
    hb[tid] = y;
    __syncthreads();

    if (tid < HH) {
        float a = b2[tid];
        for (int i = 0; i < CH; i++) a += hb[i] * w2[i * HH + tid];
        float sp = (a > 20.0f) ? a : log1pf(__expf(a));
        temp[b * HH + tid] = sp + 0.5f;
    }
}

// ---------------------------------------------------------------------------
// Flash attention (fp32). Grid: (T/128, B*H). 256 threads.
// q,k,v laid out [B,T,C] with head slice h*64..h*64+63.
// ---------------------------------------------------------------------------
#define FBM 128
#define FBN 64
#define QS 132
#define KSS 68
#define PSr 68

__global__ __launch_bounds__(256) void flash_attn(
    const float* __restrict__ q, const float* __restrict__ k, const float* __restrict__ v,
    const int* __restrict__ mask, const float* __restrict__ temp,
    float* __restrict__ out)
{
    extern __shared__ float sm[];
    float* Qt = sm;                 // [64][QS]   (d-major, 128 rows)
    float* Kt = Qt + 64 * QS;       // [64][KSS]  (d-major, 64 cols)
    float* Vs = Kt + 64 * KSS;      // [64][64]   (c-major)
    float* Ps = Vs + 64 * 64;       // [128][PSr] (r-major)

    int tid = threadIdx.x;
    int tx4 = (tid & 15) * 4;
    int ty4 = (tid >> 4) * 4;
    int bh = blockIdx.y;
    int b = bh >> 4, h = bh & 15;
    int q0 = blockIdx.x * FBM;

    const float* qbase = q + (size_t)b * TT * CC + h * DD;
    const float* kbase = k + (size_t)b * TT * CC + h * DD;
    const float* vbase = v + (size_t)b * TT * CC + h * DD;
    const int*   mbase = mask + (size_t)b * TT * TT;

    float tfac = temp[bh] * 0.125f;   // 1/sqrt(64) * temp

    // Load Q tile transposed: Qt[d][r]
    for (int idx = tid; idx < FBM * DD; idx += 256) {
        int r = idx >> 6, d = idx & 63;
        Qt[d * QS + r] = qbase[(size_t)(q0 + r) * CC + d];
    }

    float m_i[8], l_i[8], Oacc[8][4];
    #pragma unroll
    for (int i = 0; i < 8; i++) {
        m_i[i] = NEG_INF; l_i[i] = 0.0f;
        #pragma unroll
        for (int j = 0; j < 4; j++) Oacc[i][j] = 0.0f;
    }

    for (int kt = 0; kt < TT; kt += FBN) {
        __syncthreads();   // prev O-gemm done with Vs/Ps; (first iter: Qt visible)
        for (int idx = tid; idx < FBN * DD; idx += 256) {
            int c = idx >> 6, d = idx & 63;
            float kv = kbase[(size_t)(kt + c) * CC + d];
            float vv = vbase[(size_t)(kt + c) * CC + d];
            Kt[d * KSS + c] = kv;
            Vs[c * 64 + d]  = vv;
        }
        __syncthreads();

        // S[8][4] = Q tile rows x K tile cols
        float S[8][4];
        #pragma unroll
        for (int i = 0; i < 8; i++)
            #pragma unroll
            for (int j = 0; j < 4; j++) S[i][j] = 0.0f;

        #pragma unroll 8
        for (int d = 0; d < 64; d++) {
            float4 a0 = *(const float4*)&Qt[d * QS + ty4];
            float4 a1 = *(const float4*)&Qt[d * QS + 64 + ty4];
            float4 bb = *(const float4*)&Kt[d * KSS + tx4];
            float ra[8] = {a0.x, a0.y, a0.z, a0.w, a1.x, a1.y, a1.z, a1.w};
            float rb[4] = {bb.x, bb.y, bb.z, bb.w};
            #pragma unroll
            for (int i = 0; i < 8; i++)
                #pragma unroll
                for (int j = 0; j < 4; j++)
                    S[i][j] += ra[i] * rb[j];
        }

        // mask + scale*temp
        #pragma unroll
        for (int i = 0; i < 8; i++) {
            int rg = q0 + ((i < 4) ? (ty4 + i) : (64 + ty4 + i - 4));
            const int* mr = mbase + (size_t)rg * TT + kt + tx4;
            #pragma unroll
            for (int j = 0; j < 4; j++)
                S[i][j] = (mr[j] != 0) ? S[i][j] * tfac : NEG_INF;
        }

        // online softmax per row (row owned by 16 consecutive lanes)
        #pragma unroll
        for (int i = 0; i < 8; i++) {
            float mx = fmaxf(fmaxf(S[i][0], S[i][1]), fmaxf(S[i][2], S[i][3]));
            #pragma unroll
            for (int off = 8; off >= 1; off >>= 1)
                mx = fmaxf(mx, __shfl_xor_sync(0xffffffffu, mx, off, 16));
            float mnew = fmaxf(m_i[i], mx);
            float corr = __expf(m_i[i] - mnew);
            float ps = 0.0f;
            #pragma unroll
            for (int j = 0; j < 4; j++) {
                float e = __expf(S[i][j] - mnew);
                S[i][j] = e;
                ps += e;
            }
            #pragma unroll
            for (int off = 8; off >= 1; off >>= 1)
                ps += __shfl_xor_sync(0xffffffffu, ps, off, 16);
            l_i[i] = l_i[i] * corr + ps;
            m_i[i] = mnew;
            #pragma unroll
            for (int j = 0; j < 4; j++) Oacc[i][j] *= corr;
        }

        // write P to smem (row-major, conflict-free float4)
        #pragma unroll
        for (int i = 0; i < 8; i++) {
            int rl = (i < 4) ? (ty4 + i) : (64 + ty4 + i - 4);
            *(float4*)&Ps[rl * PSr + tx4] = make_float4(S[i][0], S[i][1], S[i][2], S[i][3]);
        }
        __syncthreads();

        // O += P @ V   (thread: 8 rows x 4 d-cols)
        for (int c = 0; c < 64; c += 4) {
            float4 pv[8];
            #pragma unroll
            for (int i = 0; i < 8; i++) {
                int rl = (i < 4) ? (ty4 + i) : (64 + ty4 + i - 4);
                pv[i] = *(const float4*)&Ps[rl * PSr + c];
            }
            float4 vv[4];
            #pragma unroll
            for (int cc = 0; cc < 4; cc++)
                vv[cc] = *(const float4*)&Vs[(c + cc) * 64 + tx4];
            #pragma unroll
            for (int i = 0; i < 8; i++) {
                float pr[4] = {pv[i].x, pv[i].y, pv[i].z, pv[i].w};
                #pragma unroll
                for (int cc = 0; cc < 4; cc++) {
                    Oacc[i][0] += pr[cc] * vv[cc].x;
                    Oacc[i][1] += pr[cc] * vv[cc].y;
                    Oacc[i][2] += pr[cc] * vv[cc].z;
                    Oacc[i][3] += pr[cc] * vv[cc].w;
                }
            }
        }
    }

    // normalize and write out: [B,T,C] layout
    #pragma unroll
    for (int i = 0; i < 8; i++) {
        float inv = 1.0f / l_i[i];
        int rg = q0 + ((i < 4) ? (ty4 + i) : (64 + ty4 + i - 4));
        float4 o = make_float4(Oacc[i][0] * inv, Oacc[i][1] * inv,
                               Oacc[i][2] * inv, Oacc[i][3] * inv);
        *(float4*)(out + (size_t)(b * TT + rg) * CC + h * DD + tx4) = o;
    }
}

// ---------------------------------------------------------------------------
// Final residual LN: y = LN(x + o) * g + b
// ---------------------------------------------------------------------------
__global__ __launch_bounds__(256) void final_ln(
    const float* __restrict__ x, const float* __restrict__ o,
    const float* __restrict__ g, const float* __restrict__ beta,
    float* __restrict__ out)
{
    __shared__ float sbuf[32];
    int row = blockIdx.x, tid = threadIdx.x;
    const float* xr = x + (size_t)row * CC;
    const float* orr = o + (size_t)row * CC;
    float v[4];
    #pragma unroll
    for (int i = 0; i < 4; i++) v[i] = xr[tid + i * 256] + orr[tid + i * 256];

    float s = block_reduce_sum(v[0] + v[1] + v[2] + v[3], sbuf);
    float mu = s * (1.0f / 1024.0f);
    float q = 0.0f;
    #pragma unroll
    for (int i = 0; i < 4; i++) { float d = v[i] - mu; q += d * d; }
    q = block_reduce_sum(q, sbuf);
    float rstd = rsqrtf(q * (1.0f / 1024.0f) + 1e-5f);

    float* yr = out + (size_t)row * CC;
    #pragma unroll
    for (int i = 0; i < 4; i++) {
        int c = tid + i * 256;
        yr[c] = (v[i] - mu) * rstd * g[c] + beta[c];
    }
}

// ---------------------------------------------------------------------------
// Launch
// ---------------------------------------------------------------------------
extern "C" void kernel_launch(void* const* d_in, const int* in_sizes, int n_in,
                              void* d_out, int out_size)
{
    const float* x        = (const float*)d_in[0];
    const int*   mask     = (const int*)  d_in[1];
    const float* imp_w1   = (const float*)d_in[2];
    const float* imp_b1   = (const float*)d_in[3];
    const float* imp_g    = (const float*)d_in[4];
    const float* imp_beta = (const float*)d_in[5];
    const float* imp_w2   = (const float*)d_in[6];
    const float* imp_b2   = (const float*)d_in[7];
    const float* rsn_w1   = (const float*)d_in[8];
    const float* rsn_b1   = (const float*)d_in[9];
    const float* rsn_g    = (const float*)d_in[10];
    const float* rsn_beta = (const float*)d_in[11];
    const float* rsn_w2   = (const float*)d_in[12];
    const float* rsn_b2   = (const float*)d_in[13];
    const float* q_w      = (const float*)d_in[14];
    const float* q_b      = (const float*)d_in[15];
    const float* k_w      = (const float*)d_in[16];
    const float* k_b      = (const float*)d_in[17];
    const float* v_w      = (const float*)d_in[18];
    const float* v_b      = (const float*)d_in[19];
    const float* o_w      = (const float*)d_in[20];
    const float* o_b      = (const float*)d_in[21];
    const float* tmp_w1   = (const float*)d_in[22];
    const float* tmp_b1   = (const float*)d_in[23];
    const float* tmp_g    = (const float*)d_in[24];
    const float* tmp_beta = (const float*)d_in[25];
    const float* tmp_w2   = (const float*)d_in[26];
    const float* tmp_b2   = (const float*)d_in[27];
    const float* norm_g   = (const float*)d_in[28];
    const float* norm_b   = (const float*)d_in[29];

    float *bufA, *bufB, *bufC, *bufD, *bufE, *meanb, *tempb;
    cudaGetSymbolAddress((void**)&bufA, g_bufA);
    cudaGetSymbolAddress((void**)&bufB, g_bufB);
    cudaGetSymbolAddress((void**)&bufC, g_bufC);
    cudaGetSymbolAddress((void**)&bufD, g_bufD);
    cudaGetSymbolAddress((void**)&bufE, g_bufE);
    cudaGetSymbolAddress((void**)&meanb, g_mean);
    cudaGetSymbolAddress((void**)&tempb, g_temp);

    // 1. h1 = x @ imp_w1 + b1                       [4096,512]
    sgemm_bias<<<dim3(CH/128, BT/128), 256>>>(x, imp_w1, imp_b1, bufA, BT, CH, CC);
    // 2. importance gate -> xi                       [4096,1024]
    imp_fuse<<<BT, 256>>>(bufA, imp_g, imp_beta, imp_w2, imp_b2, x, bufB);
    // 3. rsnh = xi @ rsn_w1 + b
    sgemm_bias<<<dim3(CC/128, BT/128), 256>>>(bufB, rsn_w1, rsn_b1, bufC, BT, CC, CC);
    // 4. rsnh = GELU(LN(rsnh))
    ln_gelu_1024<<<BT, 256>>>(bufC, rsn_g, rsn_beta);
    // 5. reasoned = rsnh @ rsn_w2 + b
    sgemm_bias<<<dim3(CC/128, BT/128), 256>>>(bufC, rsn_w2, rsn_b2, bufD, BT, CC, CC);
    // 6. q = reasoned @ q_w + b   (overwrites rsnh)
    sgemm_bias<<<dim3(CC/128, BT/128), 256>>>(bufD, q_w, q_b, bufC, BT, CC, CC);
    // 7. k = xi @ k_w + b
    sgemm_bias<<<dim3(CC/128, BT/128), 256>>>(bufB, k_w, k_b, bufE, BT, CC, CC);
    // 8. v = x @ v_w + b          (overwrites xi)
    sgemm_bias<<<dim3(CC/128, BT/128), 256>>>(x, v_w, v_b, bufB, BT, CC, CC);
    // 9. mean over T of reasoned
    mean_kernel<<<(BB*CC)/256, 256>>>(bufD, meanb);
    // 10. temperature
    temp_kernel<<<BB, 512>>>(meanb, tmp_w1, tmp_b1, tmp_g, tmp_beta, tmp_w2, tmp_b2, tempb);
    // 11. flash attention -> attnout (overwrites reasoned)
    {
        int smemBytes = (64*QS + 64*KSS + 64*64 + 128*PSr) * (int)sizeof(float);
        cudaFuncSetAttribute(flash_attn, cudaFuncAttributeMaxDynamicSharedMemorySize, smemBytes);
        flash_attn<<<dim3(TT/FBM, BB*HH), 256, smemBytes>>>(bufC, bufE, bufB, mask, tempb, bufD);
    }
    // 12. o = attnout @ o_w + b   (overwrites k)
    sgemm_bias<<<dim3(CC/128, BT/128), 256>>>(bufD, o_w, o_b, bufE, BT, CC, CC);
    // 13. out = LN(x + o)
    final_ln<<<BT, 256>>>(x, bufE, norm_g, norm_b, (float*)d_out);
}

// round 15
// speedup vs baseline: 1.0113x; 1.0035x over previous
#include <cuda_runtime.h>
#include <math.h>
#include <stdint.h>

// Problem constants
#define BB 2
#define TT 2048
#define CC 1024
#define HH 16
#define DD 64
#define CH 512
#define BT (BB*TT)          // 4096 rows

#define NEG_INF (__int_as_float(0xff800000))

// ---------------------------------------------------------------------------
// Scratch (device globals; reused across stages)
// ---------------------------------------------------------------------------
__device__ float g_bufA[BT*CH];    // h1
__device__ float g_bufB[BT*CC];    // xi -> v -> o
__device__ float g_bufC[BT*CC];    // rsnh -> q
__device__ float g_bufD[BT*CC];    // reasoned -> attnout
__device__ float g_bufE[BT*CC];    // k -> o (final proj)
__device__ float g_mean[BB*CC];
__device__ float g_temp[BB*HH];

// ---------------------------------------------------------------------------
// Helpers
// ---------------------------------------------------------------------------
__device__ __forceinline__ float gelu_exact(float x) {
    return 0.5f * x * (1.0f + erff(x * 0.7071067811865476f));
}

__device__ __forceinline__ float block_reduce_sum(float v, float* sbuf) {
    #pragma unroll
    for (int off = 16; off >= 1; off >>= 1)
        v += __shfl_xor_sync(0xffffffffu, v, off);
    int tid = threadIdx.x;
    int warp = tid >> 5, lane = tid & 31;
    int nw = blockDim.x >> 5;
    if (lane == 0) sbuf[warp] = v;
    __syncthreads();
    float s = (tid < nw) ? sbuf[tid] : 0.0f;
    if (warp == 0) {
        #pragma unroll
        for (int off = 16; off >= 1; off >>= 1)
            s += __shfl_xor_sync(0xffffffffu, s, off);
        if (lane == 0) sbuf[0] = s;
    }
    __syncthreads();
    float r = sbuf[0];
    __syncthreads();
    return r;
}

// ---------------------------------------------------------------------------
// SGEMM: Y[M,N] = A[M,K] @ W[K,N] + bias[N]
// 128x128x8 tile, 256 threads, 8x8 micro-tile (split 64-col groups).
// Requires M%128==0, N%128==0, K%8==0.
// ---------------------------------------------------------------------------
__global__ __launch_bounds__(256) void sgemm_bias(
    const float* __restrict__ A, const float* __restrict__ W,
    const float* __restrict__ bias, float* __restrict__ Y,
    int M, int N, int K)
{
    __shared__ float As[8][128];   // transposed A tile: As[k][m]
    __shared__ float Bs[8][128];   // Bs[k][n]

    int tid = threadIdx.x;
    int bx = blockIdx.x, by = blockIdx.y;
    int tx4 = (tid & 15) * 4;
    int ty4 = (tid >> 4) * 4;

    int a_row = tid >> 1;            // 0..127
    int a_col = (tid & 1) << 2;      // 0 or 4
    int b_row = tid >> 5;            // 0..7
    int b_col = (tid & 31) << 2;     // 0..124

    const float* Ab = A + (size_t)(by * 128) * K;
    const float* Wb = W + (size_t)(bx * 128);

    float acc[8][8];
    #pragma unroll
    for (int i = 0; i < 8; i++)
        #pragma unroll
        for (int j = 0; j < 8; j++) acc[i][j] = 0.0f;

    float4 a_next = *(const float4*)(Ab + (size_t)a_row * K + a_col);
    float4 b_next = *(const float4*)(Wb + (size_t)b_row * N + b_col);

    for (int k0 = 0; k0 < K; k0 += 8) {
        As[a_col + 0][a_row] = a_next.x;
        As[a_col + 1][a_row] = a_next.y;
        As[a_col + 2][a_row] = a_next.z;
        As[a_col + 3][a_row] = a_next.w;
        *(float4*)&Bs[b_row][b_col] = b_next;
        __syncthreads();

        if (k0 + 8 < K) {
            a_next = *(const float4*)(Ab + (size_t)a_row * K + (k0 + 8) + a_col);
            b_next = *(const float4*)(Wb + (size_t)(k0 + 8 + b_row) * N + b_col);
        }

        #pragma unroll
        for (int kk = 0; kk < 8; kk++) {
            float4 a0 = *(const float4*)&As[kk][ty4];
            float4 a1 = *(const float4*)&As[kk][64 + ty4];
            float4 b0 = *(const float4*)&Bs[kk][tx4];
            float4 b1 = *(const float4*)&Bs[kk][64 + tx4];
            float ra[8] = {a0.x, a0.y, a0.z, a0.w, a1.x, a1.y, a1.z, a1.w};
            float rb[8] = {b0.x, b0.y, b0.z, b0.w, b1.x, b1.y, b1.z, b1.w};
            #pragma unroll
            for (int i = 0; i < 8; i++)
                #pragma unroll
                for (int j = 0; j < 8; j++)
                    acc[i][j] += ra[i] * rb[j];
        }
        __syncthreads();
    }

    // Epilogue with bias
    #pragma unroll
    for (int i = 0; i < 8; i++) {
        int row = by * 128 + ((i < 4) ? (ty4 + i) : (64 + ty4 + i - 4));
        #pragma unroll
        for (int jg = 0; jg < 2; jg++) {
            int col = bx * 128 + jg * 64 + tx4;
            float4 o;
            o.x = acc[i][jg * 4 + 0] + bias[col + 0];
            o.y = acc[i][jg * 4 + 1] + bias[col + 1];
            o.z = acc[i][jg * 4 + 2] + bias[col + 2];
            o.w = acc[i][jg * 4 + 3] + bias[col + 3];
            *(float4*)(Y + (size_t)row * N + col) = o;
        }
    }
}

// ---------------------------------------------------------------------------
// Importance fuse: per row (BT rows):
//   y = GELU(LN(h1_row))   (len 512)
//   imp = max(sigmoid(dot(y, w2) + b2), 1e-6)
//   xi_row = x_row * imp   (len 1024)
// ---------------------------------------------------------------------------
__global__ __launch_bounds__(256) void imp_fuse(
    const float* __restrict__ h1, const float* __restrict__ g, const float* __restrict__ beta,
    const float* __restrict__ w2, const float* __restrict__ b2,
    const float* __restrict__ x, float* __restrict__ xi)
{
    __shared__ float sbuf[32];
    int row = blockIdx.x, tid = threadIdx.x;
    const float* hr = h1 + (size_t)row * CH;
    float v0 = hr[tid], v1 = hr[tid + 256];

    float s = block_reduce_sum(v0 + v1, sbuf);
    float mu = s * (1.0f / 512.0f);
    float d0 = v0 - mu, d1 = v1 - mu;
    float q = block_reduce_sum(d0 * d0 + d1 * d1, sbuf);
    float rstd = rsqrtf(q * (1.0f / 512.0f) + 1e-5f);

    float y0 = gelu_exact(d0 * rstd * g[tid] + beta[tid]);
    float y1 = gelu_exact(d1 * rstd * g[tid + 256] + beta[tid + 256]);

    float part = y0 * w2[tid] + y1 * w2[tid + 256];
    float dot = block_reduce_sum(part, sbuf);
    float z = dot + b2[0];
    float imp = 1.0f / (1.0f + __expf(-z));
    imp = fmaxf(imp, 1e-6f);

    const float* xr = x + (size_t)row * CC;
    float* xir = xi + (size_t)row * CC;
    #pragma unroll
    for (int i = 0; i < 4; i++)
        xir[tid + i * 256] = xr[tid + i * 256] * imp;
}

// ---------------------------------------------------------------------------
// In-place LN + GELU over rows of length 1024
// ---------------------------------------------------------------------------
__global__ __launch_bounds__(256) void ln_gelu_1024(
    float* __restrict__ h, const float* __restrict__ g, const float* __restrict__ beta)
{
    __shared__ float sbuf[32];
    int row = blockIdx.x, tid = threadIdx.x;
    float* hr = h + (size_t)row * CC;
    float v[4];
    #pragma unroll
    for (int i = 0; i < 4; i++) v[i] = hr[tid + i * 256];

    float s = block_reduce_sum(v[0] + v[1] + v[2] + v[3], sbuf);
    float mu = s * (1.0f / 1024.0f);
    float q = 0.0f;
    #pragma unroll
    for (int i = 0; i < 4; i++) { float d = v[i] - mu; q += d * d; }
    q = block_reduce_sum(q, sbuf);
    float rstd = rsqrtf(q * (1.0f / 1024.0f) + 1e-5f);

    #pragma unroll
    for (int i = 0; i < 4; i++) {
        int c = tid + i * 256;
        float y = (v[i] - mu) * rstd * g[c] + beta[c];
        hr[c] = gelu_exact(y);
    }
}

// ---------------------------------------------------------------------------
// Mean over T: reasoned[B,T,C] -> mean[B,C]
// ---------------------------------------------------------------------------
__global__ __launch_bounds__(256) void mean_kernel(
    const float* __restrict__ r, float* __restrict__ out)
{
    int idx = blockIdx.x * 256 + threadIdx.x;   // 0..2047
    int b = idx >> 10, c = idx & 1023;
    const float* p = r + (size_t)b * TT * CC + c;
    float s = 0.0f;
    #pragma unroll 8
    for (int t = 0; t < TT; t++) s += p[(size_t)t * CC];
    out[idx] = s * (1.0f / (float)TT);
}

// ---------------------------------------------------------------------------
// Temperature net: mean[B,C] -> temp[B,H]. One block per batch, 512 threads.
// ---------------------------------------------------------------------------
__global__ __launch_bounds__(512) void temp_kernel(
    const float* __restrict__ mean, const float* __restrict__ w1, const float* __restrict__ b1,
    const float* __restrict__ g, const float* __restrict__ beta,
    const float* __restrict__ w2, const float* __restrict__ b2,
    float* __restrict__ temp)
{
    __shared__ float xm[CC];
    __shared__ float hb[CH];
    __shared__ float sbuf[32];
    int b = blockIdx.x, tid = threadIdx.x;
    for (int i = tid; i < CC; i += 512) xm[i] = mean[b * CC + i];
    __syncthreads();

    float acc = b1[tid];
    #pragma unroll 8
    for (int i = 0; i < CC; i++) acc += xm[i] * w1[(size_t)i * CH + tid];

    float s = block_reduce_sum(acc, sbuf);
    float mu = s * (1.0f / 512.0f);
    float d = acc - mu;
    float q = block_reduce_sum(d * d, sbuf);
    float rstd = rsqrtf(q * (1.0f / 512.0f) + 1e-5f);
    float y = gelu_exact(d * rstd * g[tid] + beta[tid]);
    hb[tid] = y;
    __syncthreads();

    if (tid < HH) {
        float a = b2[tid];
        for (int i = 0; i < CH; i++) a += hb[i] * w2[i * HH + tid];
        float sp = (a > 20.0f) ? a : log1pf(__expf(a));
        temp[b * HH + tid] = sp + 0.5f;
    }
}

// ---------------------------------------------------------------------------
// Flash attention (fp32). Grid: (T/128, B*H). 256 threads.
// q,k,v laid out [B,T,C] with head slice h*64..h*64+63.
// ---------------------------------------------------------------------------
#define FBM 128
#define FBN 64
#define QS 132
#define KSS 68
#define PSr 68

__global__ __launch_bounds__(256) void flash_attn(
    const float* __restrict__ q, const float* __restrict__ k, const float* __restrict__ v,
    const int* __restrict__ mask, const float* __restrict__ temp,
    float* __restrict__ out)
{
    extern __shared__ float sm[];
    float* Qt = sm;                 // [64][QS]   (d-major, 128 rows)
    float* Kt = Qt + 64 * QS;       // [64][KSS]  (d-major, 64 cols)
    float* Vs = Kt + 64 * KSS;      // [64][64]   (c-major)
    float* Ps = Vs + 64 * 64;       // [128][PSr] (r-major)

    int tid = threadIdx.x;
    int tx4 = (tid & 15) * 4;
    int ty4 = (tid >> 4) * 4;
    int bh = blockIdx.y;
    int b = bh >> 4, h = bh & 15;
    int q0 = blockIdx.x * FBM;

    const float* qbase = q + (size_t)b * TT * CC + h * DD;
    const float* kbase = k + (size_t)b * TT * CC + h * DD;
    const float* vbase = v + (size_t)b * TT * CC + h * DD;
    const int*   mbase = mask + (size_t)b * TT * TT;

    float tfac = temp[bh] * 0.125f;   // 1/sqrt(64) * temp

    // Load Q tile transposed: Qt[d][r]
    for (int idx = tid; idx < FBM * DD; idx += 256) {
        int r = idx >> 6, d = idx & 63;
        Qt[d * QS + r] = qbase[(size_t)(q0 + r) * CC + d];
    }

    float m_i[8], l_i[8], Oacc[8][4];
    #pragma unroll
    for (int i = 0; i < 8; i++) {
        m_i[i] = NEG_INF; l_i[i] = 0.0f;
        #pragma unroll
        for (int j = 0; j < 4; j++) Oacc[i][j] = 0.0f;
    }

    for (int kt = 0; kt < TT; kt += FBN) {
        __syncthreads();   // prev O-gemm done with Vs/Ps; (first iter: Qt visible)
        for (int idx = tid; idx < FBN * DD; idx += 256) {
            int c = idx >> 6, d = idx & 63;
            float kv = kbase[(size_t)(kt + c) * CC + d];
            float vv = vbase[(size_t)(kt + c) * CC + d];
            Kt[d * KSS + c] = kv;
            Vs[c * 64 + d]  = vv;
        }
        __syncthreads();

        // S[8][4] = Q tile rows x K tile cols
        float S[8][4];
        #pragma unroll
        for (int i = 0; i < 8; i++)
            #pragma unroll
            for (int j = 0; j < 4; j++) S[i][j] = 0.0f;

        #pragma unroll 8
        for (int d = 0; d < 64; d++) {
            float4 a0 = *(const float4*)&Qt[d * QS + ty4];
            float4 a1 = *(const float4*)&Qt[d * QS + 64 + ty4];
            float4 bb = *(const float4*)&Kt[d * KSS + tx4];
            float ra[8] = {a0.x, a0.y, a0.z, a0.w, a1.x, a1.y, a1.z, a1.w};
            float rb[4] = {bb.x, bb.y, bb.z, bb.w};
            #pragma unroll
            for (int i = 0; i < 8; i++)
                #pragma unroll
                for (int j = 0; j < 4; j++)
                    S[i][j] += ra[i] * rb[j];
        }

        // mask + scale*temp
        #pragma unroll
        for (int i = 0; i < 8; i++) {
            int rg = q0 + ((i < 4) ? (ty4 + i) : (64 + ty4 + i - 4));
            const int* mr = mbase + (size_t)rg * TT + kt + tx4;
            #pragma unroll
            for (int j = 0; j < 4; j++)
                S[i][j] = (mr[j] != 0) ? S[i][j] * tfac : NEG_INF;
        }

        // online softmax per row (row owned by 16 consecutive lanes)
        #pragma unroll
        for (int i = 0; i < 8; i++) {
            float mx = fmaxf(fmaxf(S[i][0], S[i][1]), fmaxf(S[i][2], S[i][3]));
            #pragma unroll
            for (int off = 8; off >= 1; off >>= 1)
                mx = fmaxf(mx, __shfl_xor_sync(0xffffffffu, mx, off, 16));
            float mnew = fmaxf(m_i[i], mx);
            float corr = __expf(m_i[i] - mnew);
            float ps = 0.0f;
            #pragma unroll
            for (int j = 0; j < 4; j++) {
                float e = __expf(S[i][j] - mnew);
                S[i][j] = e;
                ps += e;
            }
            #pragma unroll
            for (int off = 8; off >= 1; off >>= 1)
                ps += __shfl_xor_sync(0xffffffffu, ps, off, 16);
            l_i[i] = l_i[i] * corr + ps;
            m_i[i] = mnew;
            #pragma unroll
            for (int j = 0; j < 4; j++) Oacc[i][j] *= corr;
        }

        // write P to smem (row-major, conflict-free float4)
        #pragma unroll
        for (int i = 0; i < 8; i++) {
            int rl = (i < 4) ? (ty4 + i) : (64 + ty4 + i - 4);
            *(float4*)&Ps[rl * PSr + tx4] = make_float4(S[i][0], S[i][1], S[i][2], S[i][3]);
        }
        __syncthreads();

        // O += P @ V   (thread: 8 rows x 4 d-cols)
        for (int c = 0; c < 64; c += 4) {
            float4 pv[8];
            #pragma unroll
            for (int i = 0; i < 8; i++) {
                int rl = (i < 4) ? (ty4 + i) : (64 + ty4 + i - 4);
                pv[i] = *(const float4*)&Ps[rl * PSr + c];
            }
            float4 vv[4];
            #pragma unroll
            for (int cc = 0; cc < 4; cc++)
                vv[cc] = *(const float4*)&Vs[(c + cc) * 64 + tx4];
            #pragma unroll
            for (int i = 0; i < 8; i++) {
                float pr[4] = {pv[i].x, pv[i].y, pv[i].z, pv[i].w};
                #pragma unroll
                for (int cc = 0; cc < 4; cc++) {
                    Oacc[i][0] += pr[cc] * vv[cc].x;
                    Oacc[i][1] += pr[cc] * vv[cc].y;
                    Oacc[i][2] += pr[cc] * vv[cc].z;
                    Oacc[i][3] += pr[cc] * vv[cc].w;
                }
            }
        }
    }

    // normalize and write out: [B,T,C] layout
    #pragma unroll
    for (int i = 0; i < 8; i++) {
        float inv = 1.0f / l_i[i];
        int rg = q0 + ((i < 4) ? (ty4 + i) : (64 + ty4 + i - 4));
        float4 o = make_float4(Oacc[i][0] * inv, Oacc[i][1] * inv,
                               Oacc[i][2] * inv, Oacc[i][3] * inv);
        *(float4*)(out + (size_t)(b * TT + rg) * CC + h * DD + tx4) = o;
    }
}

// ---------------------------------------------------------------------------
// Final residual LN: y = LN(x + o) * g + b
// ---------------------------------------------------------------------------
__global__ __launch_bounds__(256) void final_ln(
    const float* __restrict__ x, const float* __restrict__ o,
    const float* __restrict__ g, const float* __restrict__ beta,
    float* __restrict__ out)
{
    __shared__ float sbuf[32];
    int row = blockIdx.x, tid = threadIdx.x;
    const float* xr = x + (size_t)row * CC;
    const float* orr = o + (size_t)row * CC;
    float v[4];
    #pragma unroll
    for (int i = 0; i < 4; i++) v[i] = xr[tid + i * 256] + orr[tid + i * 256];

    float s = block_reduce_sum(v[0] + v[1] + v[2] + v[3], sbuf);
    float mu = s * (1.0f / 1024.0f);
    float q = 0.0f;
    #pragma unroll
    for (int i = 0; i < 4; i++) { float d = v[i] - mu; q += d * d; }
    q = block_reduce_sum(q, sbuf);
    float rstd = rsqrtf(q * (1.0f / 1024.0f) + 1e-5f);

    float* yr = out + (size_t)row * CC;
    #pragma unroll
    for (int i = 0; i < 4; i++) {
        int c = tid + i * 256;
        yr[c] = (v[i] - mu) * rstd * g[c] + beta[c];
    }
}

// ---------------------------------------------------------------------------
// Launch
// ---------------------------------------------------------------------------
extern "C" void kernel_launch(void* const* d_in, const int* in_sizes, int n_in,
                              void* d_out, int out_size)
{
    const float* x        = (const float*)d_in[0];
    const int*   mask     = (const int*)  d_in[1];
    const float* imp_w1   = (const float*)d_in[2];
    const float* imp_b1   = (const float*)d_in[3];
    const float* imp_g    = (const float*)d_in[4];
    const float* imp_beta = (const float*)d_in[5];
    const float* imp_w2   = (const float*)d_in[6];
    const float* imp_b2   = (const float*)d_in[7];
    const float* rsn_w1   = (const float*)d_in[8];
    const float* rsn_b1   = (const float*)d_in[9];
    const float* rsn_g    = (const float*)d_in[10];
    const float* rsn_beta = (const float*)d_in[11];
    const float* rsn_w2   = (const float*)d_in[12];
    const float* rsn_b2   = (const float*)d_in[13];
    const float* q_w      = (const float*)d_in[14];
    const float* q_b      = (const float*)d_in[15];
    const float* k_w      = (const float*)d_in[16];
    const float* k_b      = (const float*)d_in[17];
    const float* v_w      = (const float*)d_in[18];
    const float* v_b      = (const float*)d_in[19];
    const float* o_w      = (const float*)d_in[20];
    const float* o_b      = (const float*)d_in[21];
    const float* tmp_w1   = (const float*)d_in[22];
    const float* tmp_b1   = (const float*)d_in[23];
    const float* tmp_g    = (const float*)d_in[24];
    const float* tmp_beta = (const float*)d_in[25];
    const float* tmp_w2   = (const float*)d_in[26];
    const float* tmp_b2   = (const float*)d_in[27];
    const float* norm_g   = (const float*)d_in[28];
    const float* norm_b   = (const float*)d_in[29];

    float *bufA, *bufB, *bufC, *bufD, *bufE, *meanb, *tempb;
    cudaGetSymbolAddress((void**)&bufA, g_bufA);
    cudaGetSymbolAddress((void**)&bufB, g_bufB);
    cudaGetSymbolAddress((void**)&bufC, g_bufC);
    cudaGetSymbolAddress((void**)&bufD, g_bufD);
    cudaGetSymbolAddress((void**)&bufE, g_bufE);
    cudaGetSymbolAddress((void**)&meanb, g_mean);
    cudaGetSymbolAddress((void**)&tempb, g_temp);

    // 1. h1 = x @ imp_w1 + b1                       [4096,512]
    sgemm_bias<<<dim3(CH/128, BT/128), 256>>>(x, imp_w1, imp_b1, bufA, BT, CH, CC);
    // 2. importance gate -> xi                       [4096,1024]
    imp_fuse<<<BT, 256>>>(bufA, imp_g, imp_beta, imp_w2, imp_b2, x, bufB);
    // 3. rsnh = xi @ rsn_w1 + b
    sgemm_bias<<<dim3(CC/128, BT/128), 256>>>(bufB, rsn_w1, rsn_b1, bufC, BT, CC, CC);
    // 4. rsnh = GELU(LN(rsnh))
    ln_gelu_1024<<<BT, 256>>>(bufC, rsn_g, rsn_beta);
    // 5. reasoned = rsnh @ rsn_w2 + b
    sgemm_bias<<<dim3(CC/128, BT/128), 256>>>(bufC, rsn_w2, rsn_b2, bufD, BT, CC, CC);
    // 6. q = reasoned @ q_w + b   (overwrites rsnh)
    sgemm_bias<<<dim3(CC/128, BT/128), 256>>>(bufD, q_w, q_b, bufC, BT, CC, CC);
    // 7. k = xi @ k_w + b
    sgemm_bias<<<dim3(CC/128, BT/128), 256>>>(bufB, k_w, k_b, bufE, BT, CC, CC);
    // 8. v = x @ v_w + b          (overwrites xi)
    sgemm_bias<<<dim3(CC/128, BT/128), 256>>>(x, v_w, v_b, bufB, BT, CC, CC);
    // 9. mean over T of reasoned
    mean_kernel<<<(BB*CC)/256, 256>>>(bufD, meanb);
    // 10. temperature
    temp_kernel<<<BB, 512>>>(meanb, tmp_w1, tmp_b1, tmp_g, tmp_beta, tmp_w2, tmp_b2, tempb);
    // 11. flash attention -> attnout (overwrites reasoned)
    {
        int smemBytes = (64*QS + 64*KSS + 64*64 + 128*PSr) * (int)sizeof(float);
        cudaFuncSetAttribute(flash_attn, cudaFuncAttributeMaxDynamicSharedMemorySize, smemBytes);
        flash_attn<<<dim3(TT/FBM, BB*HH), 256, smemBytes>>>(bufC, bufE, bufB, mask, tempb, bufD);
    }
    // 12. o = attnout @ o_w + b   (overwrites k)
    sgemm_bias<<<dim3(CC/128, BT/128), 256>>>(bufD, o_w, o_b, bufE, BT, CC, CC);
    // 13. out = LN(x + o)
    final_ln<<<BT, 256>>>(x, bufE, norm_g, norm_b, (float*)d_out);
}